// round 1
// baseline (speedup 1.0000x reference)
#include <cuda_runtime.h>
#include <cuda_bf16.h>

// RobustSum L1 (IRLS, K=3) — x:(128,1024) fp32, weight:(1024,1024) fp32 -> z:(128,1024) fp32
//
// Per (b,o) pair, all state is thread-local:
//   c = z/D1;  iterate:  r_i = 1/(|x_i*W_io - c| + eps);  c = (Σ r_i·xw_i) / max(Σ r_i, 1e-12)
//   out = D1 * c
//
// Tiling: block = 8 b-rows x 64 o-cols, 256 threads, each thread owns 1 b x 2 o.
// x tile lives in smem (broadcast reads within a warp); weight streams via L1/L2.

#define B_DIM   128
#define DIN     1024
#define DOUT    1024
#define KITER   3
#define EPSILON 0.001f

#define TB 8
#define TO 64
#define NTHREADS 256

__global__ __launch_bounds__(NTHREADS, 2)
void robust_sum_kernel(const float* __restrict__ x,
                       const float* __restrict__ w,
                       float* __restrict__ out)
{
    __shared__ float xs[TB][DIN];   // 32 KB

    const int bl   = threadIdx.x >> 5;   // warp id -> local b row (0..7)
    const int lane = threadIdx.x & 31;
    const int b    = blockIdx.y * TB + bl;
    const int o0   = blockIdx.x * TO + lane * 2;

    // Stage x tile (8 x 1024 floats) coalesced: 256 threads x 8 float4 each.
    {
        const float4* src = (const float4*)(x + (size_t)blockIdx.y * TB * DIN);
        float4*       dst = (float4*)&xs[0][0];
        #pragma unroll
        for (int idx = threadIdx.x; idx < TB * DIN / 4; idx += NTHREADS) {
            dst[idx] = src[idx];
        }
    }
    __syncthreads();

    const float* wp = w + o0;   // weight[i*DOUT + o0], float2 per step

    // ---- pass 0: z = x @ W  (tracked as c = z / DIN) ----
    float s0 = 0.f, s1 = 0.f;
    #pragma unroll 8
    for (int i = 0; i < DIN; i++) {
        float  xi = xs[bl][i];
        float2 wv = __ldg((const float2*)(wp + (size_t)i * DOUT));
        s0 = fmaf(xi, wv.x, s0);
        s1 = fmaf(xi, wv.y, s1);
    }
    float c0 = s0 * (1.0f / DIN);
    float c1 = s1 * (1.0f / DIN);

    // ---- K IRLS iterations ----
    #pragma unroll 1
    for (int k = 0; k < KITER; k++) {
        float sw0 = 0.f, swx0 = 0.f;
        float sw1 = 0.f, swx1 = 0.f;
        #pragma unroll 8
        for (int i = 0; i < DIN; i++) {
            float  xi = xs[bl][i];
            float2 wv = __ldg((const float2*)(wp + (size_t)i * DOUT));
            float xw0 = xi * wv.x;
            float xw1 = xi * wv.y;
            float r0 = __fdividef(1.0f, fabsf(xw0 - c0) + EPSILON);  // MUFU.RCP
            float r1 = __fdividef(1.0f, fabsf(xw1 - c1) + EPSILON);
            sw0 += r0;  swx0 = fmaf(r0, xw0, swx0);
            sw1 += r1;  swx1 = fmaf(r1, xw1, swx1);
        }
        c0 = swx0 / fmaxf(sw0, 1e-12f);
        c1 = swx1 / fmaxf(sw1, 1e-12f);
    }

    float* op = out + (size_t)b * DOUT + o0;
    op[0] = (float)DIN * c0;
    op[1] = (float)DIN * c1;
}

extern "C" void kernel_launch(void* const* d_in, const int* in_sizes, int n_in,
                              void* d_out, int out_size)
{
    const float* x = (const float*)d_in[0];   // (128, 1024)
    const float* w = (const float*)d_in[1];   // (1024, 1024)
    float* out = (float*)d_out;               // (128, 1024)

    dim3 grid(DOUT / TO, B_DIM / TB);         // (16, 16)
    robust_sum_kernel<<<grid, NTHREADS>>>(x, w, out);
}